// round 17
// baseline (speedup 1.0000x reference)
#include <cuda_runtime.h>
#include <cstdint>

#define NROWS   32768
#define DCOLS   2048
#define C4TOT   (DCOLS / 4)          // 512 float4 per row
#define TROWS   8                    // rows per TMA tile
#define TILE_B  (TROWS * DCOLS * 4)  // 65536 bytes per tile
#define NTILES  (NROWS / TROWS)      // 4096 tiles
#define RCTAS   152                  // one CTA per SM
#define EPS     1e-6f

// Allocation-free scratch; returned to zero by the kernels themselves.
__device__ float g_u[DCOLS];
__device__ float g_s[DCOLS];
__device__ int   g_cnt[C4TOT];       // one counter per float4 column

// ---------------------------------------------------------------------------
// PTX helpers (1D bulk async copy — no tensor map needed, x is contiguous)
__device__ __forceinline__ uint32_t smem_u32(const void* p) {
    uint32_t a;
    asm("{ .reg .u64 t; cvta.to.shared.u64 t, %1; cvt.u32.u64 %0, t; }"
        : "=r"(a) : "l"(p));
    return a;
}
__device__ __forceinline__ void mbar_init(uint32_t mbar, uint32_t cnt) {
    asm volatile("mbarrier.init.shared.b64 [%0], %1;" :: "r"(mbar), "r"(cnt)
                 : "memory");
}
__device__ __forceinline__ void mbar_expect_tx(uint32_t mbar, uint32_t bytes) {
    asm volatile("mbarrier.arrive.expect_tx.shared.b64 _, [%0], %1;"
                 :: "r"(mbar), "r"(bytes) : "memory");
}
__device__ __forceinline__ void bulk_ld(uint32_t dst, const void* src,
                                        uint32_t bytes, uint32_t mbar) {
    asm volatile(
        "cp.async.bulk.shared::cta.global.mbarrier::complete_tx::bytes "
        "[%0], [%1], %2, [%3];"
        :: "r"(dst), "l"(src), "r"(bytes), "r"(mbar) : "memory");
}
__device__ __forceinline__ void mbar_wait(uint32_t mbar, uint32_t parity) {
    asm volatile(
        "{\n\t.reg .pred P;\n\t"
        "WL_%=:\n\t"
        "mbarrier.try_wait.parity.acquire.cta.shared::cta.b64 P, [%0], %1, 0x989680;\n\t"
        "@P bra.uni WD_%=;\n\t"
        "bra.uni WL_%=;\n\t"
        "WD_%=:\n\t}"
        :: "r"(mbar), "r"(parity) : "memory");
}

// ---------------------------------------------------------------------------
// Pass 1: column sum-of-squares via TMA bulk reads. 152 CTAs x 512 threads,
// double-buffered 64KB tiles (8 rows each). Thread t owns float4 column t;
// accumulators stay in registers across all tiles; 4 atomics per thread at
// the end + the proven counter/atomicExch finalize.
__global__ void __launch_bounds__(512)
reduceTMA_kernel(const float* __restrict__ x) {
    extern __shared__ __align__(128) float4 smtiles[];   // [2][TROWS*C4TOT]
    __shared__ __align__(8) unsigned long long mbars[2];

    const int tid = threadIdx.x;                         // float4 col 0..511
    const int bid = blockIdx.x;

    const uint32_t mb0 = smem_u32(&mbars[0]);
    const uint32_t mb1 = smem_u32(&mbars[1]);
    const uint32_t sm0 = smem_u32(&smtiles[0]);
    const uint32_t sm1 = sm0 + TILE_B;

    if (tid == 0) { mbar_init(mb0, 1); mbar_init(mb1, 1); }
    __syncthreads();

    // This CTA's tiles: bid, bid+RCTAS, ... (26 or 27 of them)
    const int n = (NTILES - bid + RCTAS - 1) / RCTAS;

    // Prologue: fill both buffers
    if (tid == 0) {
        mbar_expect_tx(mb0, TILE_B);
        bulk_ld(sm0, x + (size_t)bid * TROWS * DCOLS, TILE_B, mb0);
        if (n > 1) {
            mbar_expect_tx(mb1, TILE_B);
            bulk_ld(sm1, x + (size_t)(bid + RCTAS) * TROWS * DCOLS, TILE_B, mb1);
        }
    }

    float ax = 0.f, ay = 0.f, az = 0.f, aw = 0.f;

    for (int i = 0; i < n; ++i) {
        const uint32_t mb  = (i & 1) ? mb1 : mb0;
        const float4*  buf = smtiles + (i & 1) * (TROWS * C4TOT);
        mbar_wait(mb, (i >> 1) & 1);

#pragma unroll
        for (int r = 0; r < TROWS; ++r) {
            float4 v = buf[r * C4TOT + tid];
            ax = fmaf(v.x, v.x, ax); ay = fmaf(v.y, v.y, ay);
            az = fmaf(v.z, v.z, az); aw = fmaf(v.w, v.w, aw);
        }
        __syncthreads();                                  // all consumed

        if (tid == 0 && i + 2 < n) {                      // refill this buffer
            const int t = bid + (i + 2) * RCTAS;
            mbar_expect_tx(mb, TILE_B);
            bulk_ld((i & 1) ? sm1 : sm0,
                    x + (size_t)t * TROWS * DCOLS, TILE_B, mb);
        }
    }

    // Publish: 4 spread atomics per thread, then counter finalize (152 arrivals)
    const int sc = tid * 4;
    atomicAdd(&g_u[sc + 0], ax);
    atomicAdd(&g_u[sc + 1], ay);
    atomicAdd(&g_u[sc + 2], az);
    atomicAdd(&g_u[sc + 3], aw);
    __threadfence();
    if (atomicAdd(&g_cnt[tid], 1) == RCTAS - 1) {
        float t0 = atomicExch(&g_u[sc + 0], 0.0f);
        float t1 = atomicExch(&g_u[sc + 1], 0.0f);
        float t2 = atomicExch(&g_u[sc + 2], 0.0f);
        float t3 = atomicExch(&g_u[sc + 3], 0.0f);
        g_s[sc + 0] = rsqrtf(t0 + EPS);
        g_s[sc + 1] = rsqrtf(t1 + EPS);
        g_s[sc + 2] = rsqrtf(t2 + EPS);
        g_s[sc + 3] = rsqrtf(t3 + EPS);
        g_cnt[tid] = 0;                                   // replay reset
    }
}

// ---------------------------------------------------------------------------
// Pass 2: y = x * s[col]. UNCHANGED — 82.6% DRAM / 6.55 TB/s, at roofline.
__global__ void __launch_bounds__(256)
scaleAll_kernel(const float4* __restrict__ x, float4* __restrict__ y) {
    const unsigned j   = blockIdx.x * 256u + threadIdx.x;
    const int      c4  = j & (C4TOT - 1);
    const unsigned rq  = j >> 9;
    const size_t base  = (size_t)rq * C4TOT + c4;
    const size_t step  = (size_t)(NROWS / 4) * C4TOT;

    const float4 s = ((const float4*)g_s)[c4];

    float4 v0 = __ldcs(x + base);
    float4 v1 = __ldcs(x + base +     step);
    float4 v2 = __ldcs(x + base + 2 * step);
    float4 v3 = __ldcs(x + base + 3 * step);
    v0.x *= s.x; v0.y *= s.y; v0.z *= s.z; v0.w *= s.w;
    v1.x *= s.x; v1.y *= s.y; v1.z *= s.z; v1.w *= s.w;
    v2.x *= s.x; v2.y *= s.y; v2.z *= s.z; v2.w *= s.w;
    v3.x *= s.x; v3.y *= s.y; v3.z *= s.z; v3.w *= s.w;
    __stcs(y + base,            v0);
    __stcs(y + base +     step, v1);
    __stcs(y + base + 2 * step, v2);
    __stcs(y + base + 3 * step, v3);
}

// ---------------------------------------------------------------------------
extern "C" void kernel_launch(void* const* d_in, const int* in_sizes, int n_in,
                              void* d_out, int out_size) {
    const float* xf = (const float*)d_in[0];
    const float4* x = (const float4*)d_in[0];
    float4*       y = (float4*)d_out;

    static bool init = false;
    if (!init) {
        cudaFuncSetAttribute(reduceTMA_kernel,
                             cudaFuncAttributeMaxDynamicSharedMemorySize,
                             2 * TILE_B);
        init = true;
    }

    reduceTMA_kernel<<<RCTAS, 512, 2 * TILE_B>>>(xf);

    const unsigned bBlocks = (NROWS / 4) * C4TOT / 256;   // 16384
    scaleAll_kernel<<<bBlocks, 256>>>(x, y);
}